// round 2
// baseline (speedup 1.0000x reference)
#include <cuda_runtime.h>
#include <cuda_bf16.h>
#include <math.h>

// Problem constants
#define NB 2
#define HH 96
#define WW 96
#define HWP (HH*WW)          // 9216
#define CIN 256
#define BC 128

// Scratch (device globals; no allocation allowed)
__device__ float g_feat4  [(size_t)NB*512*HWP];   // relu(IN(conv_ltrb))  [N,512,HW]
__device__ float g_feat4_t[(size_t)NB*512*HWP];   // channels-last: [N,4,HW,128]
__device__ float g_align  [(size_t)NB*640*HWP];   // ltrb(512ch) + fm_short(128ch)
__device__ float g_mask   [(size_t)NB*640*HWP];   // sigmoid(conv3x3)
__device__ float g_mean   [NB*640 + NB*640];
__device__ float g_rstd   [NB*640 + NB*640];

// ---------------------------------------------------------------------------
// Tiled GEMM:  C[n] = act(A[M,K] * B[n][K,P] + bias)
// 128x128x8 tile, 256 threads, 8x8 micro-tile per thread.
// MODE 0: B plain [K,P];  MODE 1: B = B1 .* B2;  MODE 2: implicit 3x3 conv
// ACT  0: none; 1: relu; 2: sigmoid
// Requires: M % 128 == 0 handled by grid.y, P % 128 == 0, K % 8 == 0.
// ---------------------------------------------------------------------------
#define BM 128
#define BN 128
#define BK 8

template<int MODE, int ACT>
__global__ __launch_bounds__(256)
void gemm_kernel(const float* __restrict__ A,
                 const float* __restrict__ B1,
                 const float* __restrict__ B2,
                 const float* __restrict__ bias,
                 float* __restrict__ C,
                 int M, int K, int P,
                 long ldBn, long ldCn)
{
    const int n  = blockIdx.z;
    const int m0 = blockIdx.y * BM;
    const int p0 = blockIdx.x * BN;
    const float* Bn1 = B1 + (long)n * ldBn;
    const float* Bn2 = (MODE == 1) ? (B2 + (long)n * ldBn) : nullptr;
    float* Cn = C + (long)n * ldCn;

    __shared__ float sA[BK][BM];
    __shared__ float sB[BK][BN];

    const int tid = threadIdx.x;
    const int tx = tid & 15;      // pixel sub-tile (8 px)
    const int ty = tid >> 4;      // M sub-tile (8 rows)

    // A-tile loader: 128 rows x 8 k; one float4 per thread
    const int arow = tid >> 1;
    const int acol = (tid & 1) * 4;
    // B-tile loader (MODE 0/1): 8 k-rows x 128 p; one float4 per thread
    const int brow = tid >> 5;
    const int bcol = (tid & 31) * 4;

    float acc[8][8] = {};

    for (int k0 = 0; k0 < K; k0 += BK) {
        // ---- load A tile (transposed into sA[k][m]) ----
        float4 a4 = *(const float4*)&A[(long)(m0 + arow) * K + k0 + acol];
        sA[acol + 0][arow] = a4.x;
        sA[acol + 1][arow] = a4.y;
        sA[acol + 2][arow] = a4.z;
        sA[acol + 3][arow] = a4.w;

        // ---- load B tile ----
        if (MODE == 0) {
            *(float4*)&sB[brow][bcol] =
                *(const float4*)&Bn1[(long)(k0 + brow) * P + p0 + bcol];
        } else if (MODE == 1) {
            long off = (long)(k0 + brow) * P + p0 + bcol;
            float4 b4 = *(const float4*)&Bn1[off];
            float4 c4 = *(const float4*)&Bn2[off];
            b4.x *= c4.x; b4.y *= c4.y; b4.z *= c4.z; b4.w *= c4.w;
            *(float4*)&sB[brow][bcol] = b4;
        } else {
            #pragma unroll
            for (int i = 0; i < 4; i++) {
                int e = tid + i * 256;
                int k = e >> 7, p = e & 127;
                int kk = k0 + k, pp = p0 + p;
                int ci = kk / 9, t = kk - ci * 9;
                int kh = t / 3,  kw = t - kh * 3;
                int y = pp / WW, x = pp - y * WW;
                int yy = y + kh - 1, xx = x + kw - 1;
                sB[k][p] = (yy >= 0 && yy < HH && xx >= 0 && xx < WW)
                           ? Bn1[((long)ci * HH + yy) * WW + xx] : 0.f;
            }
        }
        __syncthreads();

        // ---- 8 k-steps of 8x8 outer product ----
        #pragma unroll
        for (int k = 0; k < BK; k++) {
            float av[8], bv[8];
            *(float4*)&av[0] = *(const float4*)&sA[k][ty * 8];
            *(float4*)&av[4] = *(const float4*)&sA[k][ty * 8 + 4];
            *(float4*)&bv[0] = *(const float4*)&sB[k][tx * 8];
            *(float4*)&bv[4] = *(const float4*)&sB[k][tx * 8 + 4];
            #pragma unroll
            for (int i = 0; i < 8; i++)
                #pragma unroll
                for (int j = 0; j < 8; j++)
                    acc[i][j] = fmaf(av[i], bv[j], acc[i][j]);
        }
        __syncthreads();
    }

    // ---- epilogue ----
    #pragma unroll
    for (int i = 0; i < 8; i++) {
        int m = m0 + ty * 8 + i;
        float bs = bias[m];
        float vals[8];
        #pragma unroll
        for (int j = 0; j < 8; j++) {
            float v = acc[i][j] + bs;
            if (ACT == 1) v = fmaxf(v, 0.f);
            else if (ACT == 2) v = 1.f / (1.f + expf(-v));
            vals[j] = v;
        }
        float* cp = &Cn[(long)m * P + p0 + tx * 8];
        *(float4*)&cp[0] = make_float4(vals[0], vals[1], vals[2], vals[3]);
        *(float4*)&cp[4] = make_float4(vals[4], vals[5], vals[6], vals[7]);
    }
}

// ---------------------------------------------------------------------------
// Instance-norm stats: one block per (c, n)
// ---------------------------------------------------------------------------
__global__ void stats_kernel(const float* __restrict__ x, long strideN, int C,
                             float* __restrict__ mean, float* __restrict__ rstd)
{
    int c = blockIdx.x, n = blockIdx.y;
    const float* p = x + (long)n * strideN + (long)c * HWP;
    float s = 0.f, s2 = 0.f;
    for (int i = threadIdx.x; i < HWP; i += 256) {
        float v = p[i];
        s += v; s2 += v * v;
    }
    #pragma unroll
    for (int o = 16; o > 0; o >>= 1) {
        s  += __shfl_down_sync(0xffffffffu, s,  o);
        s2 += __shfl_down_sync(0xffffffffu, s2, o);
    }
    __shared__ float sh1[8], sh2[8];
    int w = threadIdx.x >> 5, l = threadIdx.x & 31;
    if (l == 0) { sh1[w] = s; sh2[w] = s2; }
    __syncthreads();
    if (threadIdx.x == 0) {
        float S = 0.f, S2 = 0.f;
        #pragma unroll
        for (int i = 0; i < 8; i++) { S += sh1[i]; S2 += sh2[i]; }
        float m   = S / (float)HWP;
        float var = S2 / (float)HWP - m * m;
        mean[n * C + c] = m;
        rstd[n * C + c] = rsqrtf(var + 1e-5f);
    }
}

__global__ void inorm_relu_kernel(float* __restrict__ x, long strideN, int C,
                                  const float* __restrict__ mean,
                                  const float* __restrict__ rstd)
{
    int c = blockIdx.y, n = blockIdx.z;
    float m = mean[n * C + c], r = rstd[n * C + c];
    float* p = x + (long)n * strideN + (long)c * HWP;
    for (int i = blockIdx.x * blockDim.x + threadIdx.x; i < HWP;
         i += gridDim.x * blockDim.x)
        p[i] = fmaxf((p[i] - m) * r, 0.f);
}

// ---------------------------------------------------------------------------
// Transpose feat4 [N][4*128][HW] -> [N][4][HW][128] (channels-last per group)
// ---------------------------------------------------------------------------
__global__ void transpose_kernel(const float* __restrict__ in,
                                 float* __restrict__ out)
{
    __shared__ float tile[32][33];
    int g = blockIdx.z;                      // n*4 + border group
    const float* ip = in  + (long)g * 128 * HWP;
    float*       op = out + (long)g * HWP * 128;
    int p0 = blockIdx.x * 32, c0 = blockIdx.y * 32;
    int tx = threadIdx.x, ty = threadIdx.y;  // 32 x 8
    #pragma unroll
    for (int i = 0; i < 32; i += 8)
        tile[ty + i][tx] = ip[(long)(c0 + ty + i) * HWP + p0 + tx];
    __syncthreads();
    #pragma unroll
    for (int i = 0; i < 32; i += 8)
        op[(long)(p0 + ty + i) * 128 + c0 + tx] = tile[tx][ty + i];
}

// ---------------------------------------------------------------------------
// BorderAlign: block = (pixel p, border b, n); 128 threads = channels
// Writes directly into g_align in the reference's reshaped channel layout:
//   flat offset within image = c*4*HW + p*4 + b   (== [640,HW] view)
// ---------------------------------------------------------------------------
__global__ void border_align_kernel(const float* __restrict__ ft,   // [N][4][HW][128]
                                    const float* __restrict__ boxes,// [N][HW][4]
                                    float* __restrict__ out)        // [N][640*HW]
{
    int p = blockIdx.x, b = blockIdx.y, n = blockIdx.z;
    int c = threadIdx.x;
    const float* bx = boxes + ((long)n * HWP + p) * 4;
    float x1 = bx[0], y1 = bx[1], x2 = bx[2], y2 = bx[3];
    float bw = (x2 - x1) / 10.f, bh = (y2 - y1) / 10.f;
    float sx, sy, dx, dy;
    if      (b == 0) { sx = x1; sy = y1; dx = bw;  dy = 0.f; }
    else if (b == 1) { sx = x1; sy = y1; dx = 0.f; dy = bh;  }
    else if (b == 2) { sx = x1; sy = y2; dx = bw;  dy = 0.f; }
    else             { sx = x2; sy = y1; dx = 0.f; dy = bh;  }

    const float* f = ft + ((long)(n * 4 + b) * HWP) * 128 + c;
    float best = -INFINITY;
    #pragma unroll
    for (int i = 0; i <= 10; i++) {
        float x = sx + dx * (float)i;
        float y = sy + dy * (float)i;
        bool valid = (x >= -1.f) && (x <= (float)WW) && (y >= -1.f) && (y <= (float)HH);
        float xc = fminf(fmaxf(x, 0.f), (float)(WW - 1));
        float yc = fminf(fmaxf(y, 0.f), (float)(HH - 1));
        int x0  = min((int)floorf(xc), WW - 1);
        int y0  = min((int)floorf(yc), HH - 1);
        int x1i = min(x0 + 1, WW - 1);
        int y1i = min(y0 + 1, HH - 1);
        float lx = (x0 >= WW - 1) ? 0.f : (xc - (float)x0);
        float ly = (y0 >= HH - 1) ? 0.f : (yc - (float)y0);
        float hx = 1.f - lx, hy = 1.f - ly;
        float v00 = f[((long)y0  * WW + x0 ) * 128];
        float v01 = f[((long)y0  * WW + x1i) * 128];
        float v10 = f[((long)y1i * WW + x0 ) * 128];
        float v11 = f[((long)y1i * WW + x1i) * 128];
        float val = v00 * (hy * hx) + v01 * (hy * lx)
                  + v10 * (ly * hx) + v11 * (ly * lx);
        val = valid ? val : 0.f;
        best = fmaxf(best, val);
    }
    out[(long)n * 640 * HWP + (long)c * 4 * HWP + p * 4 + b] = best;
}

// ---------------------------------------------------------------------------
extern "C" void kernel_launch(void* const* d_in, const int* in_sizes, int n_in,
                              void* d_out, int out_size)
{
    const float* feature  = (const float*)d_in[0];
    const float* boxes    = (const float*)d_in[1];
    // d_in[2] = wh (unused)
    const float* w_cur    = (const float*)d_in[3];
    const float* b_cur    = (const float*)d_in[4];
    const float* w_ltrb   = (const float*)d_in[5];
    const float* b_ltrb   = (const float*)d_in[6];
    const float* w_mask   = (const float*)d_in[7];
    const float* b_mask   = (const float*)d_in[8];
    const float* w_border = (const float*)d_in[9];
    const float* b_border = (const float*)d_in[10];
    float* out = (float*)d_out;

    float *feat4, *feat4_t, *align, *maskb, *meanp, *rstdp;
    cudaGetSymbolAddress((void**)&feat4,   g_feat4);
    cudaGetSymbolAddress((void**)&feat4_t, g_feat4_t);
    cudaGetSymbolAddress((void**)&align,   g_align);
    cudaGetSymbolAddress((void**)&maskb,   g_mask);
    cudaGetSymbolAddress((void**)&meanp,   g_mean);
    cudaGetSymbolAddress((void**)&rstdp,   g_rstd);

    const long sFeat  = (long)CIN * HWP;   // per-n feature stride
    const long sF4    = (long)512 * HWP;
    const long sAl    = (long)640 * HWP;
    const long sOut   = (long)256 * HWP;

    // 1) fm_short raw conv -> align channels [512..640)
    gemm_kernel<0,0><<<dim3(HWP/BN, 128/BM, NB), 256>>>(
        w_cur, feature, nullptr, b_cur, align + 512L*HWP,
        128, CIN, HWP, sFeat, sAl);

    // 2) feat4 raw conv
    gemm_kernel<0,0><<<dim3(HWP/BN, 512/BM, NB), 256>>>(
        w_ltrb, feature, nullptr, b_ltrb, feat4,
        512, CIN, HWP, sFeat, sF4);

    // 3) instance-norm stats + normalize+relu (feat4, fm_short)
    stats_kernel<<<dim3(512, NB), 256>>>(feat4, sF4, 512, meanp, rstdp);
    stats_kernel<<<dim3(128, NB), 256>>>(align + 512L*HWP, sAl, 128,
                                         meanp + NB*640, rstdp + NB*640);
    inorm_relu_kernel<<<dim3(36, 512, NB), 256>>>(feat4, sF4, 512, meanp, rstdp);
    inorm_relu_kernel<<<dim3(36, 128, NB), 256>>>(align + 512L*HWP, sAl, 128,
                                                  meanp + NB*640, rstdp + NB*640);

    // 4) channels-last transpose of feat4 for border-align gathers
    transpose_kernel<<<dim3(HWP/32, 4, NB*4), dim3(32, 8)>>>(feat4, feat4_t);

    // 5) border align -> align channels [0..512) (reference reshape layout)
    border_align_kernel<<<dim3(HWP, 4, NB), 128>>>(feat4_t, boxes, align);

    // 6) mask = sigmoid(conv3x3(feat4))  [implicit GEMM, K = 512*9]
    gemm_kernel<2,2><<<dim3(HWP/BN, 640/BM, NB), 256>>>(
        w_mask, feat4, nullptr, b_mask, maskb,
        640, 512*9, HWP, sF4, sAl);

    // 7) out = relu(conv1x1(align .* mask))
    gemm_kernel<1,1><<<dim3(HWP/BN, 256/BM, NB), 256>>>(
        w_border, align, maskb, b_border, out,
        256, 640, HWP, sAl, sOut);
}

// round 3
// speedup vs baseline: 2.0036x; 2.0036x over previous
#include <cuda_runtime.h>
#include <cuda_bf16.h>
#include <math.h>

// Problem constants
#define NB 2
#define HH 96
#define WW 96
#define HWP (HH*WW)          // 9216
#define CIN 256
#define BC 128

// Scratch (device globals; no allocation allowed)
__device__ float g_feat4  [(size_t)NB*512*HWP];   // relu(IN(conv_ltrb))  [N,512,HW]
__device__ float g_feat4_t[(size_t)NB*512*HWP];   // channels-last: [N,4,HW,128]
__device__ float g_align  [(size_t)NB*640*HWP];   // ltrb(512ch) + fm_short(128ch)
__device__ float g_mask   [(size_t)NB*640*HWP];   // sigmoid(conv3x3)
__device__ float g_mean   [NB*640 + NB*640];
__device__ float g_rstd   [NB*640 + NB*640];

// ---------------------------------------------------------------------------
// TF32 helpers
// ---------------------------------------------------------------------------
__device__ __forceinline__ float tf32r(float x) {
    unsigned u;
    asm("cvt.rna.tf32.f32 %0, %1;" : "=r"(u) : "f"(x));
    return __uint_as_float(u);
}

__device__ __forceinline__ void mma_tf32(float d[4], const unsigned a[4],
                                         const unsigned b[2]) {
    asm volatile(
        "mma.sync.aligned.m16n8k8.row.col.f32.tf32.tf32.f32 "
        "{%0,%1,%2,%3}, {%4,%5,%6,%7}, {%8,%9}, {%0,%1,%2,%3};\n"
        : "+f"(d[0]), "+f"(d[1]), "+f"(d[2]), "+f"(d[3])
        : "r"(a[0]), "r"(a[1]), "r"(a[2]), "r"(a[3]),
          "r"(b[0]), "r"(b[1]));
}

// ---------------------------------------------------------------------------
// Tensor-core GEMM:  C[n] = act(A[M,K] * B[n][K,P] + bias)   (TF32 inputs)
// 128x128x16 block tile, 256 threads (8 warps, 2x4), warp tile 64x32,
// m16n8k8 mma fragments loaded from padded shared memory.
// MODE 0: B plain [K,P];  MODE 1: B = B1 .* B2;  MODE 2: implicit 3x3 conv
// ACT  0: none; 1: relu; 2: sigmoid
// Requires: M % 128 == 0 (grid.y), P % 128 == 0, K % 16 == 0.
// ---------------------------------------------------------------------------
#define BM 128
#define BN 128
#define BK 16
#define SAPAD (BM + 4)
#define SBPAD (BN + 4)

template<int MODE, int ACT>
__global__ __launch_bounds__(256, 2)
void gemm_tc(const float* __restrict__ A,
             const float* __restrict__ B1,
             const float* __restrict__ B2,
             const float* __restrict__ bias,
             float* __restrict__ C,
             int M, int K, int P,
             long ldBn, long ldCn)
{
    const int n  = blockIdx.z;
    const int m0 = blockIdx.y * BM;
    const int p0 = blockIdx.x * BN;
    const float* Bn1 = B1 + (long)n * ldBn;
    const float* Bn2 = (MODE == 1) ? (B2 + (long)n * ldBn) : nullptr;
    float* Cn = C + (long)n * ldCn;

    __shared__ float sA[BK][SAPAD];
    __shared__ float sB[BK][SBPAD];

    const int tid  = threadIdx.x;
    const int lane = tid & 31;
    const int warp = tid >> 5;
    const int wm = warp >> 2;       // 0..1  (64-row slab)
    const int wn = warp & 3;        // 0..3  (32-col slab)
    const int g  = lane >> 2;       // group id 0..7
    const int t  = lane & 3;        // thread-in-group 0..3

    float acc[4][4][4];
    #pragma unroll
    for (int i = 0; i < 4; i++)
        #pragma unroll
        for (int j = 0; j < 4; j++)
            #pragma unroll
            for (int r = 0; r < 4; r++) acc[i][j][r] = 0.f;

    for (int k0 = 0; k0 < K; k0 += BK) {
        // ---- load A tile: [BM rows x BK k], store transposed sA[k][m] ----
        #pragma unroll
        for (int i = 0; i < 2; i++) {
            int idx = tid + i * 256;
            int r = idx >> 2, c4 = (idx & 3) * 4;
            float4 a4 = *(const float4*)&A[(long)(m0 + r) * K + k0 + c4];
            sA[c4 + 0][r] = tf32r(a4.x);
            sA[c4 + 1][r] = tf32r(a4.y);
            sA[c4 + 2][r] = tf32r(a4.z);
            sA[c4 + 3][r] = tf32r(a4.w);
        }
        // ---- load B tile: sB[k][p] ----
        if (MODE == 0 || MODE == 1) {
            #pragma unroll
            for (int i = 0; i < 2; i++) {
                int idx = tid + i * 256;
                int kr = idx >> 5, pc = (idx & 31) * 4;
                long off = (long)(k0 + kr) * P + p0 + pc;
                float4 b4 = *(const float4*)&Bn1[off];
                if (MODE == 1) {
                    float4 c4 = *(const float4*)&Bn2[off];
                    b4.x *= c4.x; b4.y *= c4.y; b4.z *= c4.z; b4.w *= c4.w;
                }
                b4.x = tf32r(b4.x); b4.y = tf32r(b4.y);
                b4.z = tf32r(b4.z); b4.w = tf32r(b4.w);
                *(float4*)&sB[kr][pc] = b4;
            }
        } else {
            #pragma unroll
            for (int i = 0; i < 8; i++) {
                int e = tid + i * 256;
                int k = e >> 7, p = e & 127;
                int kk = k0 + k, pp = p0 + p;
                int ci = kk / 9, tt = kk - ci * 9;
                int kh = tt / 3, kw = tt - kh * 3;
                int y = pp / WW, x = pp - y * WW;
                int yy = y + kh - 1, xx = x + kw - 1;
                float v = (yy >= 0 && yy < HH && xx >= 0 && xx < WW)
                          ? Bn1[((long)ci * HH + yy) * WW + xx] : 0.f;
                sB[k][p] = tf32r(v);
            }
        }
        __syncthreads();

        // ---- 2 k8-steps of 4x4 m16n8k8 tiles ----
        #pragma unroll
        for (int ks = 0; ks < 2; ks++) {
            unsigned af[4][4];
            #pragma unroll
            for (int mt = 0; mt < 4; mt++) {
                int mb = wm * 64 + mt * 16;
                af[mt][0] = __float_as_uint(sA[ks*8 + t    ][mb + g    ]);
                af[mt][1] = __float_as_uint(sA[ks*8 + t    ][mb + g + 8]);
                af[mt][2] = __float_as_uint(sA[ks*8 + t + 4][mb + g    ]);
                af[mt][3] = __float_as_uint(sA[ks*8 + t + 4][mb + g + 8]);
            }
            unsigned bf[4][2];
            #pragma unroll
            for (int nt = 0; nt < 4; nt++) {
                int nb = wn * 32 + nt * 8;
                bf[nt][0] = __float_as_uint(sB[ks*8 + t    ][nb + g]);
                bf[nt][1] = __float_as_uint(sB[ks*8 + t + 4][nb + g]);
            }
            #pragma unroll
            for (int mt = 0; mt < 4; mt++)
                #pragma unroll
                for (int nt = 0; nt < 4; nt++)
                    mma_tf32(acc[mt][nt], af[mt], bf[nt]);
        }
        __syncthreads();
    }

    // ---- epilogue: bias + activation, float2 stores ----
    #pragma unroll
    for (int mt = 0; mt < 4; mt++) {
        #pragma unroll
        for (int half = 0; half < 2; half++) {
            int row = m0 + wm * 64 + mt * 16 + g + half * 8;
            float bs = bias[row];
            #pragma unroll
            for (int nt = 0; nt < 4; nt++) {
                int col = p0 + wn * 32 + nt * 8 + t * 2;
                float v0 = acc[mt][nt][half * 2 + 0] + bs;
                float v1 = acc[mt][nt][half * 2 + 1] + bs;
                if (ACT == 1) { v0 = fmaxf(v0, 0.f); v1 = fmaxf(v1, 0.f); }
                else if (ACT == 2) {
                    v0 = 1.f / (1.f + expf(-v0));
                    v1 = 1.f / (1.f + expf(-v1));
                }
                *(float2*)&Cn[(long)row * P + col] = make_float2(v0, v1);
            }
        }
    }
}

// ---------------------------------------------------------------------------
// Instance-norm stats: one block per (c, n)
// ---------------------------------------------------------------------------
__global__ void stats_kernel(const float* __restrict__ x, long strideN, int C,
                             float* __restrict__ mean, float* __restrict__ rstd)
{
    int c = blockIdx.x, n = blockIdx.y;
    const float* p = x + (long)n * strideN + (long)c * HWP;
    float s = 0.f, s2 = 0.f;
    for (int i = threadIdx.x; i < HWP; i += 256) {
        float v = p[i];
        s += v; s2 += v * v;
    }
    #pragma unroll
    for (int o = 16; o > 0; o >>= 1) {
        s  += __shfl_down_sync(0xffffffffu, s,  o);
        s2 += __shfl_down_sync(0xffffffffu, s2, o);
    }
    __shared__ float sh1[8], sh2[8];
    int w = threadIdx.x >> 5, l = threadIdx.x & 31;
    if (l == 0) { sh1[w] = s; sh2[w] = s2; }
    __syncthreads();
    if (threadIdx.x == 0) {
        float S = 0.f, S2 = 0.f;
        #pragma unroll
        for (int i = 0; i < 8; i++) { S += sh1[i]; S2 += sh2[i]; }
        float m   = S / (float)HWP;
        float var = S2 / (float)HWP - m * m;
        mean[n * C + c] = m;
        rstd[n * C + c] = rsqrtf(var + 1e-5f);
    }
}

__global__ void inorm_relu_kernel(float* __restrict__ x, long strideN, int C,
                                  const float* __restrict__ mean,
                                  const float* __restrict__ rstd)
{
    int c = blockIdx.y, n = blockIdx.z;
    float m = mean[n * C + c], r = rstd[n * C + c];
    float* p = x + (long)n * strideN + (long)c * HWP;
    for (int i = blockIdx.x * blockDim.x + threadIdx.x; i < HWP;
         i += gridDim.x * blockDim.x)
        p[i] = fmaxf((p[i] - m) * r, 0.f);
}

// ---------------------------------------------------------------------------
// Transpose feat4 [N][4*128][HW] -> [N][4][HW][128] (channels-last per group)
// ---------------------------------------------------------------------------
__global__ void transpose_kernel(const float* __restrict__ in,
                                 float* __restrict__ out)
{
    __shared__ float tile[32][33];
    int g = blockIdx.z;                      // n*4 + border group
    const float* ip = in  + (long)g * 128 * HWP;
    float*       op = out + (long)g * HWP * 128;
    int p0 = blockIdx.x * 32, c0 = blockIdx.y * 32;
    int tx = threadIdx.x, ty = threadIdx.y;  // 32 x 8
    #pragma unroll
    for (int i = 0; i < 32; i += 8)
        tile[ty + i][tx] = ip[(long)(c0 + ty + i) * HWP + p0 + tx];
    __syncthreads();
    #pragma unroll
    for (int i = 0; i < 32; i += 8)
        op[(long)(p0 + ty + i) * 128 + c0 + tx] = tile[tx][ty + i];
}

// ---------------------------------------------------------------------------
// BorderAlign: block = (pixel p, border b, n); 128 threads = channels
// Writes directly into g_align in the reference's reshaped channel layout:
//   flat offset within image = c*4*HW + p*4 + b   (== [640,HW] view)
// ---------------------------------------------------------------------------
__global__ void border_align_kernel(const float* __restrict__ ft,   // [N][4][HW][128]
                                    const float* __restrict__ boxes,// [N][HW][4]
                                    float* __restrict__ out)        // [N][640*HW]
{
    int p = blockIdx.x, b = blockIdx.y, n = blockIdx.z;
    int c = threadIdx.x;
    const float* bx = boxes + ((long)n * HWP + p) * 4;
    float x1 = bx[0], y1 = bx[1], x2 = bx[2], y2 = bx[3];
    float bw = (x2 - x1) / 10.f, bh = (y2 - y1) / 10.f;
    float sx, sy, dx, dy;
    if      (b == 0) { sx = x1; sy = y1; dx = bw;  dy = 0.f; }
    else if (b == 1) { sx = x1; sy = y1; dx = 0.f; dy = bh;  }
    else if (b == 2) { sx = x1; sy = y2; dx = bw;  dy = 0.f; }
    else             { sx = x2; sy = y1; dx = 0.f; dy = bh;  }

    const float* f = ft + ((long)(n * 4 + b) * HWP) * 128 + c;
    float best = -INFINITY;
    #pragma unroll
    for (int i = 0; i <= 10; i++) {
        float x = sx + dx * (float)i;
        float y = sy + dy * (float)i;
        bool valid = (x >= -1.f) && (x <= (float)WW) && (y >= -1.f) && (y <= (float)HH);
        float xc = fminf(fmaxf(x, 0.f), (float)(WW - 1));
        float yc = fminf(fmaxf(y, 0.f), (float)(HH - 1));
        int x0  = min((int)floorf(xc), WW - 1);
        int y0  = min((int)floorf(yc), HH - 1);
        int x1i = min(x0 + 1, WW - 1);
        int y1i = min(y0 + 1, HH - 1);
        float lx = (x0 >= WW - 1) ? 0.f : (xc - (float)x0);
        float ly = (y0 >= HH - 1) ? 0.f : (yc - (float)y0);
        float hx = 1.f - lx, hy = 1.f - ly;
        float v00 = f[((long)y0  * WW + x0 ) * 128];
        float v01 = f[((long)y0  * WW + x1i) * 128];
        float v10 = f[((long)y1i * WW + x0 ) * 128];
        float v11 = f[((long)y1i * WW + x1i) * 128];
        float val = v00 * (hy * hx) + v01 * (hy * lx)
                  + v10 * (ly * hx) + v11 * (ly * lx);
        val = valid ? val : 0.f;
        best = fmaxf(best, val);
    }
    out[(long)n * 640 * HWP + (long)c * 4 * HWP + p * 4 + b] = best;
}

// ---------------------------------------------------------------------------
extern "C" void kernel_launch(void* const* d_in, const int* in_sizes, int n_in,
                              void* d_out, int out_size)
{
    const float* feature  = (const float*)d_in[0];
    const float* boxes    = (const float*)d_in[1];
    // d_in[2] = wh (unused)
    const float* w_cur    = (const float*)d_in[3];
    const float* b_cur    = (const float*)d_in[4];
    const float* w_ltrb   = (const float*)d_in[5];
    const float* b_ltrb   = (const float*)d_in[6];
    const float* w_mask   = (const float*)d_in[7];
    const float* b_mask   = (const float*)d_in[8];
    const float* w_border = (const float*)d_in[9];
    const float* b_border = (const float*)d_in[10];
    float* out = (float*)d_out;

    float *feat4, *feat4_t, *align, *maskb, *meanp, *rstdp;
    cudaGetSymbolAddress((void**)&feat4,   g_feat4);
    cudaGetSymbolAddress((void**)&feat4_t, g_feat4_t);
    cudaGetSymbolAddress((void**)&align,   g_align);
    cudaGetSymbolAddress((void**)&maskb,   g_mask);
    cudaGetSymbolAddress((void**)&meanp,   g_mean);
    cudaGetSymbolAddress((void**)&rstdp,   g_rstd);

    const long sFeat  = (long)CIN * HWP;   // per-n feature stride
    const long sF4    = (long)512 * HWP;
    const long sAl    = (long)640 * HWP;
    const long sOut   = (long)256 * HWP;

    // 1) fm_short raw conv -> align channels [512..640)
    gemm_tc<0,0><<<dim3(HWP/BN, 128/BM, NB), 256>>>(
        w_cur, feature, nullptr, b_cur, align + 512L*HWP,
        128, CIN, HWP, sFeat, sAl);

    // 2) feat4 raw conv
    gemm_tc<0,0><<<dim3(HWP/BN, 512/BM, NB), 256>>>(
        w_ltrb, feature, nullptr, b_ltrb, feat4,
        512, CIN, HWP, sFeat, sF4);

    // 3) instance-norm stats + normalize+relu (feat4, fm_short)
    stats_kernel<<<dim3(512, NB), 256>>>(feat4, sF4, 512, meanp, rstdp);
    stats_kernel<<<dim3(128, NB), 256>>>(align + 512L*HWP, sAl, 128,
                                         meanp + NB*640, rstdp + NB*640);
    inorm_relu_kernel<<<dim3(36, 512, NB), 256>>>(feat4, sF4, 512, meanp, rstdp);
    inorm_relu_kernel<<<dim3(36, 128, NB), 256>>>(align + 512L*HWP, sAl, 128,
                                                  meanp + NB*640, rstdp + NB*640);

    // 4) channels-last transpose of feat4 for border-align gathers
    transpose_kernel<<<dim3(HWP/32, 4, NB*4), dim3(32, 8)>>>(feat4, feat4_t);

    // 5) border align -> align channels [0..512) (reference reshape layout)
    border_align_kernel<<<dim3(HWP, 4, NB), 128>>>(feat4_t, boxes, align);

    // 6) mask = sigmoid(conv3x3(feat4))  [implicit GEMM, K = 512*9]
    gemm_tc<2,2><<<dim3(HWP/BN, 640/BM, NB), 256>>>(
        w_mask, feat4, nullptr, b_mask, maskb,
        640, 512*9, HWP, sF4, sAl);

    // 7) out = relu(conv1x1(align .* mask))
    gemm_tc<1,1><<<dim3(HWP/BN, 256/BM, NB), 256>>>(
        w_border, align, maskb, b_border, out,
        256, 640, HWP, sAl, sOut);
}

// round 4
// speedup vs baseline: 2.1305x; 1.0634x over previous
#include <cuda_runtime.h>
#include <cuda_bf16.h>
#include <math.h>

// Problem constants
#define NB 2
#define HH 96
#define WW 96
#define HWP (HH*WW)          // 9216
#define CIN 256
#define BC 128

// Scratch (device globals; no allocation allowed)
__device__ float g_feat4  [(size_t)NB*512*HWP];   // relu(IN(conv_ltrb))  [N,512,HW]
__device__ float g_feat4_t[(size_t)NB*512*HWP];   // channels-last: [N,4,HW,128]
__device__ float g_align  [(size_t)NB*640*HWP];   // ltrb(512ch) + fm_short(128ch)
__device__ float g_mask   [(size_t)NB*640*HWP];   // sigmoid(conv3x3)
__device__ float g_mean   [NB*640];
__device__ float g_rstd   [NB*640];

// ---------------------------------------------------------------------------
// TF32 helpers
// ---------------------------------------------------------------------------
__device__ __forceinline__ float tf32r(float x) {
    unsigned u;
    asm("cvt.rna.tf32.f32 %0, %1;" : "=r"(u) : "f"(x));
    return __uint_as_float(u);
}

__device__ __forceinline__ void mma_tf32(float d[4], const unsigned a[4],
                                         const unsigned b[2]) {
    asm volatile(
        "mma.sync.aligned.m16n8k8.row.col.f32.tf32.tf32.f32 "
        "{%0,%1,%2,%3}, {%4,%5,%6,%7}, {%8,%9}, {%0,%1,%2,%3};\n"
        : "+f"(d[0]), "+f"(d[1]), "+f"(d[2]), "+f"(d[3])
        : "r"(a[0]), "r"(a[1]), "r"(a[2]), "r"(a[3]),
          "r"(b[0]), "r"(b[1]));
}

// ---------------------------------------------------------------------------
// Tensor-core GEMM with register-staged double buffering.
// C[n] = act(A[M,K] * B[n][K,P] + bias), TF32 inputs (rna), fp32 accum.
// 128x128x16 block tile, 256 threads (8 warps 2x4), warp tile 64x32.
// MODE 0: B plain [K,P];  MODE 1: B = B1 .* B2;  MODE 2: implicit 3x3 conv
// ACT  0: none; 1: relu; 2: sigmoid
// Requires: M % 128 == 0 (grid.y), P % 128 == 0, K % 16 == 0, K >= 32.
// ---------------------------------------------------------------------------
#define BM 128
#define BN 128
#define BK 16
#define SAPAD (BM + 4)
#define SBPAD (BN + 4)

template<int MODE, int ACT>
__global__ __launch_bounds__(256, 2)
void gemm_tc(const float* __restrict__ A,
             const float* __restrict__ B1,
             const float* __restrict__ B2,
             const float* __restrict__ bias,
             float* __restrict__ C,
             int M, int K, int P,
             long ldBn, long ldCn)
{
    const int n  = blockIdx.z;
    const int m0 = blockIdx.y * BM;
    const int p0 = blockIdx.x * BN;
    const float* Bn1 = B1 + (long)n * ldBn;
    const float* Bn2 = (MODE == 1) ? (B2 + (long)n * ldBn) : nullptr;
    float* Cn = C + (long)n * ldCn;

    __shared__ float sA[2][BK][SAPAD];
    __shared__ float sB[2][BK][SBPAD];

    const int tid  = threadIdx.x;
    const int lane = tid & 31;
    const int warp = tid >> 5;
    const int wm = warp >> 2;       // 0..1  (64-row slab)
    const int wn = warp & 3;        // 0..3  (32-col slab)
    const int g  = lane >> 2;       // group id 0..7
    const int t  = lane & 3;        // thread-in-group 0..3

    // Loader mapping
    const int arow = tid >> 2;           // 0..63; rows arow, arow+64
    const int acol = (tid & 3) * 4;      // k sub-offset
    const int brow = tid >> 5;           // 0..7;  rows brow, brow+8
    const int bcol = lane * 4;           // 0..124

    float acc[4][4][4] = {};

    float4 stA[2];
    float4 stB[2];
    float  stV[8];

    auto LDG = [&](int k0) {
        #pragma unroll
        for (int i = 0; i < 2; i++)
            stA[i] = *(const float4*)&A[(long)(m0 + arow + i * 64) * K + k0 + acol];
        if (MODE == 0) {
            #pragma unroll
            for (int i = 0; i < 2; i++)
                stB[i] = *(const float4*)&Bn1[(long)(k0 + brow + i * 8) * P + p0 + bcol];
        } else if (MODE == 1) {
            #pragma unroll
            for (int i = 0; i < 2; i++) {
                long off = (long)(k0 + brow + i * 8) * P + p0 + bcol;
                float4 x = *(const float4*)&Bn1[off];
                float4 y = *(const float4*)&Bn2[off];
                x.x *= y.x; x.y *= y.y; x.z *= y.z; x.w *= y.w;
                stB[i] = x;
            }
        } else {
            #pragma unroll
            for (int i = 0; i < 8; i++) {
                int e = tid + i * 256;
                int k = e >> 7, p = e & 127;
                int kk = k0 + k, pp = p0 + p;
                int ci = kk / 9, tt = kk - ci * 9;
                int kh = tt / 3, kw = tt - kh * 3;
                int y = pp / WW, x = pp - y * WW;
                int yy = y + kh - 1, xx = x + kw - 1;
                stV[i] = (yy >= 0 && yy < HH && xx >= 0 && xx < WW)
                         ? Bn1[((long)ci * HH + yy) * WW + xx] : 0.f;
            }
        }
    };

    auto STS = [&](int buf) {
        #pragma unroll
        for (int i = 0; i < 2; i++) {
            int r = arow + i * 64;
            sA[buf][acol + 0][r] = tf32r(stA[i].x);
            sA[buf][acol + 1][r] = tf32r(stA[i].y);
            sA[buf][acol + 2][r] = tf32r(stA[i].z);
            sA[buf][acol + 3][r] = tf32r(stA[i].w);
        }
        if (MODE == 0 || MODE == 1) {
            #pragma unroll
            for (int i = 0; i < 2; i++) {
                float4 x = stB[i];
                x.x = tf32r(x.x); x.y = tf32r(x.y);
                x.z = tf32r(x.z); x.w = tf32r(x.w);
                *(float4*)&sB[buf][brow + i * 8][bcol] = x;
            }
        } else {
            #pragma unroll
            for (int i = 0; i < 8; i++) {
                int e = tid + i * 256;
                int k = e >> 7, p = e & 127;
                sB[buf][k][p] = tf32r(stV[i]);
            }
        }
    };

    auto COMPUTE = [&](int buf) {
        #pragma unroll
        for (int ks = 0; ks < 2; ks++) {
            unsigned af[4][4];
            #pragma unroll
            for (int mt = 0; mt < 4; mt++) {
                int mb = wm * 64 + mt * 16;
                af[mt][0] = __float_as_uint(sA[buf][ks*8 + t    ][mb + g    ]);
                af[mt][1] = __float_as_uint(sA[buf][ks*8 + t    ][mb + g + 8]);
                af[mt][2] = __float_as_uint(sA[buf][ks*8 + t + 4][mb + g    ]);
                af[mt][3] = __float_as_uint(sA[buf][ks*8 + t + 4][mb + g + 8]);
            }
            unsigned bf[4][2];
            #pragma unroll
            for (int nt = 0; nt < 4; nt++) {
                int nb = wn * 32 + nt * 8;
                bf[nt][0] = __float_as_uint(sB[buf][ks*8 + t    ][nb + g]);
                bf[nt][1] = __float_as_uint(sB[buf][ks*8 + t + 4][nb + g]);
            }
            #pragma unroll
            for (int mt = 0; mt < 4; mt++)
                #pragma unroll
                for (int nt = 0; nt < 4; nt++)
                    mma_tf32(acc[mt][nt], af[mt], bf[nt]);
        }
    };

    // ---- pipelined mainloop ----
    LDG(0); STS(0); __syncthreads();
    int buf = 0;
    for (int k0 = BK; k0 < K; k0 += BK) {
        LDG(k0);           // prefetch next tile into registers
        COMPUTE(buf);      // compute current tile (hides LDG latency)
        STS(buf ^ 1);      // commit next tile
        __syncthreads();
        buf ^= 1;
    }
    COMPUTE(buf);

    // ---- epilogue: bias + activation, float2 stores ----
    #pragma unroll
    for (int mt = 0; mt < 4; mt++) {
        #pragma unroll
        for (int half = 0; half < 2; half++) {
            int row = m0 + wm * 64 + mt * 16 + g + half * 8;
            float bs = bias[row];
            #pragma unroll
            for (int nt = 0; nt < 4; nt++) {
                int col = p0 + wn * 32 + nt * 8 + t * 2;
                float v0 = acc[mt][nt][half * 2 + 0] + bs;
                float v1 = acc[mt][nt][half * 2 + 1] + bs;
                if (ACT == 1) { v0 = fmaxf(v0, 0.f); v1 = fmaxf(v1, 0.f); }
                else if (ACT == 2) {
                    v0 = 1.f / (1.f + expf(-v0));
                    v1 = 1.f / (1.f + expf(-v1));
                }
                *(float2*)&Cn[(long)row * P + col] = make_float2(v0, v1);
            }
        }
    }
}

// ---------------------------------------------------------------------------
// Combined instance-norm stats for feat4 (c<512) and fm_short (c in [512,640))
// one block per (c, n); mean/rstd indexed n*640 + c
// ---------------------------------------------------------------------------
__global__ void stats_kernel(const float* __restrict__ feat4,
                             const float* __restrict__ alignb,
                             float* __restrict__ mean, float* __restrict__ rstd)
{
    int c = blockIdx.x, n = blockIdx.y;
    const float* p = (c < 512)
        ? feat4  + (long)n * (512L*HWP) + (long)c * HWP
        : alignb + (long)n * (640L*HWP) + (long)c * HWP;  // fm_short lives at c in align
    float s = 0.f, s2 = 0.f;
    for (int i = threadIdx.x; i < HWP; i += 256) {
        float v = p[i];
        s += v; s2 += v * v;
    }
    #pragma unroll
    for (int o = 16; o > 0; o >>= 1) {
        s  += __shfl_down_sync(0xffffffffu, s,  o);
        s2 += __shfl_down_sync(0xffffffffu, s2, o);
    }
    __shared__ float sh1[8], sh2[8];
    int w = threadIdx.x >> 5, l = threadIdx.x & 31;
    if (l == 0) { sh1[w] = s; sh2[w] = s2; }
    __syncthreads();
    if (threadIdx.x == 0) {
        float S = 0.f, S2 = 0.f;
        #pragma unroll
        for (int i = 0; i < 8; i++) { S += sh1[i]; S2 += sh2[i]; }
        float m   = S / (float)HWP;
        float var = S2 / (float)HWP - m * m;
        mean[n * 640 + c] = m;
        rstd[n * 640 + c] = rsqrtf(var + 1e-5f);
    }
}

__global__ void inorm_relu_kernel(float* __restrict__ feat4,
                                  float* __restrict__ alignb,
                                  const float* __restrict__ mean,
                                  const float* __restrict__ rstd)
{
    int c = blockIdx.y, n = blockIdx.z;
    float m = mean[n * 640 + c], r = rstd[n * 640 + c];
    float* p = (c < 512)
        ? feat4  + (long)n * (512L*HWP) + (long)c * HWP
        : alignb + (long)n * (640L*HWP) + (long)c * HWP;
    for (int i = blockIdx.x * blockDim.x + threadIdx.x; i < HWP;
         i += gridDim.x * blockDim.x)
        p[i] = fmaxf((p[i] - m) * r, 0.f);
}

// ---------------------------------------------------------------------------
// Transpose feat4 [N][4*128][HW] -> [N][4][HW][128] (channels-last per group)
// ---------------------------------------------------------------------------
__global__ void transpose_kernel(const float* __restrict__ in,
                                 float* __restrict__ out)
{
    __shared__ float tile[32][33];
    int g = blockIdx.z;                      // n*4 + border group
    const float* ip = in  + (long)g * 128 * HWP;
    float*       op = out + (long)g * HWP * 128;
    int p0 = blockIdx.x * 32, c0 = blockIdx.y * 32;
    int tx = threadIdx.x, ty = threadIdx.y;  // 32 x 8
    #pragma unroll
    for (int i = 0; i < 32; i += 8)
        tile[ty + i][tx] = ip[(long)(c0 + ty + i) * HWP + p0 + tx];
    __syncthreads();
    #pragma unroll
    for (int i = 0; i < 32; i += 8)
        op[(long)(p0 + ty + i) * 128 + c0 + tx] = tile[tx][ty + i];
}

// ---------------------------------------------------------------------------
// BorderAlign: block = (pixel p, border b, n); 128 threads = channels
// ---------------------------------------------------------------------------
__global__ void border_align_kernel(const float* __restrict__ ft,   // [N][4][HW][128]
                                    const float* __restrict__ boxes,// [N][HW][4]
                                    float* __restrict__ out)        // [N][640*HW]
{
    int p = blockIdx.x, b = blockIdx.y, n = blockIdx.z;
    int c = threadIdx.x;
    const float* bx = boxes + ((long)n * HWP + p) * 4;
    float x1 = bx[0], y1 = bx[1], x2 = bx[2], y2 = bx[3];
    float bw = (x2 - x1) / 10.f, bh = (y2 - y1) / 10.f;
    float sx, sy, dx, dy;
    if      (b == 0) { sx = x1; sy = y1; dx = bw;  dy = 0.f; }
    else if (b == 1) { sx = x1; sy = y1; dx = 0.f; dy = bh;  }
    else if (b == 2) { sx = x1; sy = y2; dx = bw;  dy = 0.f; }
    else             { sx = x2; sy = y1; dx = 0.f; dy = bh;  }

    const float* f = ft + ((long)(n * 4 + b) * HWP) * 128 + c;
    float best = -INFINITY;
    #pragma unroll
    for (int i = 0; i <= 10; i++) {
        float x = sx + dx * (float)i;
        float y = sy + dy * (float)i;
        bool valid = (x >= -1.f) && (x <= (float)WW) && (y >= -1.f) && (y <= (float)HH);
        float xc = fminf(fmaxf(x, 0.f), (float)(WW - 1));
        float yc = fminf(fmaxf(y, 0.f), (float)(HH - 1));
        int x0  = min((int)floorf(xc), WW - 1);
        int y0  = min((int)floorf(yc), HH - 1);
        int x1i = min(x0 + 1, WW - 1);
        int y1i = min(y0 + 1, HH - 1);
        float lx = (x0 >= WW - 1) ? 0.f : (xc - (float)x0);
        float ly = (y0 >= HH - 1) ? 0.f : (yc - (float)y0);
        float hx = 1.f - lx, hy = 1.f - ly;
        float v00 = f[((long)y0  * WW + x0 ) * 128];
        float v01 = f[((long)y0  * WW + x1i) * 128];
        float v10 = f[((long)y1i * WW + x0 ) * 128];
        float v11 = f[((long)y1i * WW + x1i) * 128];
        float val = v00 * (hy * hx) + v01 * (hy * lx)
                  + v10 * (ly * hx) + v11 * (ly * lx);
        val = valid ? val : 0.f;
        best = fmaxf(best, val);
    }
    out[(long)n * 640 * HWP + (long)c * 4 * HWP + p * 4 + b] = best;
}

// ---------------------------------------------------------------------------
extern "C" void kernel_launch(void* const* d_in, const int* in_sizes, int n_in,
                              void* d_out, int out_size)
{
    const float* feature  = (const float*)d_in[0];
    const float* boxes    = (const float*)d_in[1];
    // d_in[2] = wh (unused)
    const float* w_cur    = (const float*)d_in[3];
    const float* b_cur    = (const float*)d_in[4];
    const float* w_ltrb   = (const float*)d_in[5];
    const float* b_ltrb   = (const float*)d_in[6];
    const float* w_mask   = (const float*)d_in[7];
    const float* b_mask   = (const float*)d_in[8];
    const float* w_border = (const float*)d_in[9];
    const float* b_border = (const float*)d_in[10];
    float* out = (float*)d_out;

    float *feat4, *feat4_t, *align, *maskb, *meanp, *rstdp;
    cudaGetSymbolAddress((void**)&feat4,   g_feat4);
    cudaGetSymbolAddress((void**)&feat4_t, g_feat4_t);
    cudaGetSymbolAddress((void**)&align,   g_align);
    cudaGetSymbolAddress((void**)&maskb,   g_mask);
    cudaGetSymbolAddress((void**)&meanp,   g_mean);
    cudaGetSymbolAddress((void**)&rstdp,   g_rstd);

    const long sFeat  = (long)CIN * HWP;
    const long sF4    = (long)512 * HWP;
    const long sAl    = (long)640 * HWP;
    const long sOut   = (long)256 * HWP;

    // Launch order chosen so conv3x3 implicit GEMM is launch index 5 (ncu -s 5 -c 1).
    // 0) fm_short raw conv -> align channels [512..640)
    gemm_tc<0,0><<<dim3(HWP/BN, 128/BM, NB), 256>>>(
        w_cur, feature, nullptr, b_cur, align + 512L*HWP,
        128, CIN, HWP, sFeat, sAl);

    // 1) feat4 raw conv
    gemm_tc<0,0><<<dim3(HWP/BN, 512/BM, NB), 256>>>(
        w_ltrb, feature, nullptr, b_ltrb, feat4,
        512, CIN, HWP, sFeat, sF4);

    // 2) combined instance-norm stats; 3) combined normalize+relu
    stats_kernel<<<dim3(640, NB), 256>>>(feat4, align, meanp, rstdp);
    inorm_relu_kernel<<<dim3(36, 640, NB), 256>>>(feat4, align, meanp, rstdp);

    // 4) channels-last transpose of feat4 for border-align gathers
    transpose_kernel<<<dim3(HWP/32, 4, NB*4), dim3(32, 8)>>>(feat4, feat4_t);

    // 5) mask = sigmoid(conv3x3(feat4))  [implicit GEMM, K = 512*9] — PROFILED
    gemm_tc<2,2><<<dim3(HWP/BN, 640/BM, NB), 256>>>(
        w_mask, feat4, nullptr, b_mask, maskb,
        640, 512*9, HWP, sF4, sAl);

    // 6) border align -> align channels [0..512)
    border_align_kernel<<<dim3(HWP, 4, NB), 128>>>(feat4_t, boxes, align);

    // 7) out = relu(conv1x1(align .* mask))
    gemm_tc<1,1><<<dim3(HWP/BN, 256/BM, NB), 256>>>(
        w_border, align, maskb, b_border, out,
        256, 640, HWP, sAl, sOut);
}

// round 6
// speedup vs baseline: 2.6749x; 1.2555x over previous
#include <cuda_runtime.h>
#include <cuda_bf16.h>
#include <cstdint>
#include <math.h>

// Problem constants
#define NB 2
#define HH 96
#define WW 96
#define HWP (HH*WW)          // 9216
#define CIN 256
#define BC 128

// Scratch (device globals; no allocation allowed)
__device__ float g_feat4  [(size_t)NB*512*HWP];   // relu(IN(conv_ltrb))  [N,512,HW]
__device__ float g_feat4_t[(size_t)NB*512*HWP];   // channels-last: [N,4,HW,128]
__device__ float g_align  [(size_t)NB*640*HWP];   // ltrb(512ch) + fm_short(128ch)
__device__ float g_mask   [(size_t)NB*640*HWP];   // sigmoid(conv3x3)
__device__ float g_mean   [NB*640];
__device__ float g_rstd   [NB*640];

// ---------------------------------------------------------------------------
// TF32 helpers
// ---------------------------------------------------------------------------
__device__ __forceinline__ float tf32r(float x) {
    unsigned u;
    asm("cvt.rna.tf32.f32 %0, %1;" : "=r"(u) : "f"(x));
    return __uint_as_float(u);
}

__device__ __forceinline__ void mma_tf32(float d[4], const unsigned a[4],
                                         const unsigned b[2]) {
    asm volatile(
        "mma.sync.aligned.m16n8k8.row.col.f32.tf32.tf32.f32 "
        "{%0,%1,%2,%3}, {%4,%5,%6,%7}, {%8,%9}, {%0,%1,%2,%3};\n"
        : "+f"(d[0]), "+f"(d[1]), "+f"(d[2]), "+f"(d[3])
        : "r"(a[0]), "r"(a[1]), "r"(a[2]), "r"(a[3]),
          "r"(b[0]), "r"(b[1]));
}

// ---------------------------------------------------------------------------
// Tensor-core GEMM, register-staged double buffering.
// C[n] = act(A[M,K] * B[n][K,P] + bias), TF32 inputs (rna), fp32 accum.
// 128x128x16 block tile, 256 threads (8 warps 2x4), warp tile 64x32.
// A in smem [m][k] (stride 20) for ldmatrix; B in smem [k][p] stride 136
// (conflict-free scalar fragment loads).
// MODE 0: B plain [K,P];  MODE 1: B = B1 .* B2;  MODE 2: implicit 3x3 conv
// ACT  0: none; 1: relu; 2: sigmoid
// Requires: M % 128 == 0 (grid.y), P % 128 == 0, K % 16 == 0, K >= 32.
// ---------------------------------------------------------------------------
#define BM 128
#define BN 128
#define BK 16
#define SAK 20           // sA row stride (floats): 16B-aligned rows, cf ldmatrix
#define SBPAD 136        // sB row stride: 136 mod 32 = 8 -> conflict-free frags

template<int MODE, int ACT>
__global__ __launch_bounds__(256, 2)
void gemm_tc(const float* __restrict__ A,
             const float* __restrict__ B1,
             const float* __restrict__ B2,
             const float* __restrict__ bias,
             float* __restrict__ C,
             int M, int K, int P,
             long ldBn, long ldCn)
{
    const int n  = blockIdx.z;
    const int m0 = blockIdx.y * BM;
    const int p0 = blockIdx.x * BN;
    const float* Bn1 = B1 + (long)n * ldBn;
    const float* Bn2 = (MODE == 1) ? (B2 + (long)n * ldBn) : nullptr;
    float* Cn = C + (long)n * ldCn;

    __shared__ alignas(16) float sA[2][BM][SAK];
    __shared__ alignas(16) float sB[2][BK][SBPAD];

    const int tid  = threadIdx.x;
    const int lane = tid & 31;
    const int warp = tid >> 5;
    const int wm = warp >> 2;       // 0..1  (64-row slab)
    const int wn = warp & 3;        // 0..3  (32-col slab)
    const int g  = lane >> 2;       // group id 0..7
    const int t  = lane & 3;        // thread-in-group 0..3

    // Loader mapping
    const int arow = tid >> 2;           // 0..63; rows arow, arow+64
    const int acol = (tid & 3) * 4;      // k sub-offset
    const int brow = tid >> 5;           // 0..7;  rows brow, brow+8
    const int bcol = lane * 4;           // 0..124

    // MODE 2: pixel coords fixed per thread ((tid+256i)&127 == tid&127)
    int cx = 0, cy = 0;
    if (MODE == 2) {
        int pp = p0 + (tid & 127);
        cy = pp / WW;
        cx = pp - cy * WW;
    }

    uint32_t sAu32;
    {
        void* gp = (void*)&sA[0][0][0];
        sAu32 = (uint32_t)__cvta_generic_to_shared(gp);
    }

    float acc[4][4][4] = {};

    float4 stA[2];
    float4 stB[2];
    float  stV[8];

    auto LDG = [&](int k0) {
        #pragma unroll
        for (int i = 0; i < 2; i++)
            stA[i] = *(const float4*)&A[(long)(m0 + arow + i * 64) * K + k0 + acol];
        if (MODE == 0) {
            #pragma unroll
            for (int i = 0; i < 2; i++)
                stB[i] = *(const float4*)&Bn1[(long)(k0 + brow + i * 8) * P + p0 + bcol];
        } else if (MODE == 1) {
            #pragma unroll
            for (int i = 0; i < 2; i++) {
                long off = (long)(k0 + brow + i * 8) * P + p0 + bcol;
                float4 x = *(const float4*)&Bn1[off];
                float4 y = *(const float4*)&Bn2[off];
                x.x *= y.x; x.y *= y.y; x.z *= y.z; x.w *= y.w;
                stB[i] = x;
            }
        } else {
            const int kbase = tid >> 7;   // 0 or 1
            #pragma unroll
            for (int i = 0; i < 8; i++) {
                int kk = k0 + kbase + 2 * i;
                int ci = (kk * 7282) >> 16;          // exact kk/9 for kk<4608
                int tt = kk - ci * 9;
                int kh = (tt >= 6) ? 2 : ((tt >= 3) ? 1 : 0);
                int kw = tt - kh * 3;
                int yy = cy + kh - 1, xx = cx + kw - 1;
                stV[i] = ((unsigned)yy < HH && (unsigned)xx < WW)
                         ? Bn1[((long)ci * HH + yy) * WW + xx] : 0.f;
            }
        }
    };

    auto STS = [&](int buf) {
        #pragma unroll
        for (int i = 0; i < 2; i++) {
            float4 x = stA[i];
            x.x = tf32r(x.x); x.y = tf32r(x.y);
            x.z = tf32r(x.z); x.w = tf32r(x.w);
            *(float4*)&sA[buf][arow + i * 64][acol] = x;   // [m][k], direct copy
        }
        if (MODE == 0 || MODE == 1) {
            #pragma unroll
            for (int i = 0; i < 2; i++) {
                float4 x = stB[i];
                x.x = tf32r(x.x); x.y = tf32r(x.y);
                x.z = tf32r(x.z); x.w = tf32r(x.w);
                *(float4*)&sB[buf][brow + i * 8][bcol] = x;
            }
        } else {
            const int kbase = tid >> 7;
            const int p = tid & 127;
            #pragma unroll
            for (int i = 0; i < 8; i++)
                sB[buf][kbase + 2 * i][p] = tf32r(stV[i]);
        }
    };

    auto COMPUTE = [&](int buf) {
        const uint32_t sAbase = sAu32 + (uint32_t)buf * (BM * SAK * 4);
        const int rowsel = lane & 15;
        const int colhi  = (lane >> 4) * 4;
        #pragma unroll
        for (int ks = 0; ks < 2; ks++) {
            unsigned af[4][4];
            #pragma unroll
            for (int mt = 0; mt < 4; mt++) {
                int mb = wm * 64 + mt * 16;
                uint32_t addr = sAbase +
                    (uint32_t)(((mb + rowsel) * SAK + ks * 8 + colhi) * 4);
                asm volatile(
                    "ldmatrix.sync.aligned.m8n8.x4.shared.b16 {%0,%1,%2,%3}, [%4];"
                    : "=r"(af[mt][0]), "=r"(af[mt][1]),
                      "=r"(af[mt][2]), "=r"(af[mt][3])
                    : "r"(addr));
            }
            unsigned bf[4][2];
            #pragma unroll
            for (int nt = 0; nt < 4; nt++) {
                int nb = wn * 32 + nt * 8;
                bf[nt][0] = __float_as_uint(sB[buf][ks*8 + t    ][nb + g]);
                bf[nt][1] = __float_as_uint(sB[buf][ks*8 + t + 4][nb + g]);
            }
            #pragma unroll
            for (int mt = 0; mt < 4; mt++)
                #pragma unroll
                for (int nt = 0; nt < 4; nt++)
                    mma_tf32(acc[mt][nt], af[mt], bf[nt]);
        }
    };

    // ---- pipelined mainloop ----
    LDG(0); STS(0); __syncthreads();
    int buf = 0;
    for (int k0 = BK; k0 < K; k0 += BK) {
        LDG(k0);           // prefetch next tile into registers
        COMPUTE(buf);      // compute current tile
        STS(buf ^ 1);      // commit next tile
        __syncthreads();
        buf ^= 1;
    }
    COMPUTE(buf);

    // ---- epilogue: bias + activation, float2 stores ----
    #pragma unroll
    for (int mt = 0; mt < 4; mt++) {
        #pragma unroll
        for (int half = 0; half < 2; half++) {
            int row = m0 + wm * 64 + mt * 16 + g + half * 8;
            float bs = bias[row];
            #pragma unroll
            for (int nt = 0; nt < 4; nt++) {
                int col = p0 + wn * 32 + nt * 8 + t * 2;
                float v0 = acc[mt][nt][half * 2 + 0] + bs;
                float v1 = acc[mt][nt][half * 2 + 1] + bs;
                if (ACT == 1) { v0 = fmaxf(v0, 0.f); v1 = fmaxf(v1, 0.f); }
                else if (ACT == 2) {
                    v0 = 1.f / (1.f + expf(-v0));
                    v1 = 1.f / (1.f + expf(-v1));
                }
                *(float2*)&Cn[(long)row * P + col] = make_float2(v0, v1);
            }
        }
    }
}

// ---------------------------------------------------------------------------
// Combined instance-norm stats for feat4 (c<512) and fm_short (c in [512,640))
// ---------------------------------------------------------------------------
__global__ void stats_kernel(const float* __restrict__ feat4,
                             const float* __restrict__ alignb,
                             float* __restrict__ mean, float* __restrict__ rstd)
{
    int c = blockIdx.x, n = blockIdx.y;
    const float* p = (c < 512)
        ? feat4  + (long)n * (512L*HWP) + (long)c * HWP
        : alignb + (long)n * (640L*HWP) + (long)c * HWP;
    float s = 0.f, s2 = 0.f;
    for (int i = threadIdx.x; i < HWP; i += 256) {
        float v = p[i];
        s += v; s2 += v * v;
    }
    #pragma unroll
    for (int o = 16; o > 0; o >>= 1) {
        s  += __shfl_down_sync(0xffffffffu, s,  o);
        s2 += __shfl_down_sync(0xffffffffu, s2, o);
    }
    __shared__ float sh1[8], sh2[8];
    int w = threadIdx.x >> 5, l = threadIdx.x & 31;
    if (l == 0) { sh1[w] = s; sh2[w] = s2; }
    __syncthreads();
    if (threadIdx.x == 0) {
        float S = 0.f, S2 = 0.f;
        #pragma unroll
        for (int i = 0; i < 8; i++) { S += sh1[i]; S2 += sh2[i]; }
        float m   = S / (float)HWP;
        float var = S2 / (float)HWP - m * m;
        mean[n * 640 + c] = m;
        rstd[n * 640 + c] = rsqrtf(var + 1e-5f);
    }
}

__global__ void inorm_relu_kernel(float* __restrict__ feat4,
                                  float* __restrict__ alignb,
                                  const float* __restrict__ mean,
                                  const float* __restrict__ rstd)
{
    int c = blockIdx.y, n = blockIdx.z;
    float m = mean[n * 640 + c], r = rstd[n * 640 + c];
    float* p = (c < 512)
        ? feat4  + (long)n * (512L*HWP) + (long)c * HWP
        : alignb + (long)n * (640L*HWP) + (long)c * HWP;
    for (int i = blockIdx.x * blockDim.x + threadIdx.x; i < HWP;
         i += gridDim.x * blockDim.x)
        p[i] = fmaxf((p[i] - m) * r, 0.f);
}

// ---------------------------------------------------------------------------
// Transpose feat4 [N][4*128][HW] -> [N][4][HW][128] (channels-last per group)
// ---------------------------------------------------------------------------
__global__ void transpose_kernel(const float* __restrict__ in,
                                 float* __restrict__ out)
{
    __shared__ float tile[32][33];
    int g = blockIdx.z;                      // n*4 + border group
    const float* ip = in  + (long)g * 128 * HWP;
    float*       op = out + (long)g * HWP * 128;
    int p0 = blockIdx.x * 32, c0 = blockIdx.y * 32;
    int tx = threadIdx.x, ty = threadIdx.y;  // 32 x 8
    #pragma unroll
    for (int i = 0; i < 32; i += 8)
        tile[ty + i][tx] = ip[(long)(c0 + ty + i) * HWP + p0 + tx];
    __syncthreads();
    #pragma unroll
    for (int i = 0; i < 32; i += 8)
        op[(long)(p0 + ty + i) * 128 + c0 + tx] = tile[tx][ty + i];
}

// ---------------------------------------------------------------------------
// BorderAlign: block = (pixel p, border b, n); 128 threads = channels
// ---------------------------------------------------------------------------
__global__ void border_align_kernel(const float* __restrict__ ft,   // [N][4][HW][128]
                                    const float* __restrict__ boxes,// [N][HW][4]
                                    float* __restrict__ out)        // [N][640*HW]
{
    int p = blockIdx.x, b = blockIdx.y, n = blockIdx.z;
    int c = threadIdx.x;
    const float* bx = boxes + ((long)n * HWP + p) * 4;
    float x1 = bx[0], y1 = bx[1], x2 = bx[2], y2 = bx[3];
    float bw = (x2 - x1) / 10.f, bh = (y2 - y1) / 10.f;
    float sx, sy, dx, dy;
    if      (b == 0) { sx = x1; sy = y1; dx = bw;  dy = 0.f; }
    else if (b == 1) { sx = x1; sy = y1; dx = 0.f; dy = bh;  }
    else if (b == 2) { sx = x1; sy = y2; dx = bw;  dy = 0.f; }
    else             { sx = x2; sy = y1; dx = 0.f; dy = bh;  }

    const float* f = ft + ((long)(n * 4 + b) * HWP) * 128 + c;
    float best = -INFINITY;
    #pragma unroll
    for (int i = 0; i <= 10; i++) {
        float x = sx + dx * (float)i;
        float y = sy + dy * (float)i;
        bool valid = (x >= -1.f) && (x <= (float)WW) && (y >= -1.f) && (y <= (float)HH);
        float xc = fminf(fmaxf(x, 0.f), (float)(WW - 1));
        float yc = fminf(fmaxf(y, 0.f), (float)(HH - 1));
        int x0  = min((int)floorf(xc), WW - 1);
        int y0  = min((int)floorf(yc), HH - 1);
        int x1i = min(x0 + 1, WW - 1);
        int y1i = min(y0 + 1, HH - 1);
        float lx = (x0 >= WW - 1) ? 0.f : (xc - (float)x0);
        float ly = (y0 >= HH - 1) ? 0.f : (yc - (float)y0);
        float hx = 1.f - lx, hy = 1.f - ly;
        float v00 = f[((long)y0  * WW + x0 ) * 128];
        float v01 = f[((long)y0  * WW + x1i) * 128];
        float v10 = f[((long)y1i * WW + x0 ) * 128];
        float v11 = f[((long)y1i * WW + x1i) * 128];
        float val = v00 * (hy * hx) + v01 * (hy * lx)
                  + v10 * (ly * hx) + v11 * (ly * lx);
        val = valid ? val : 0.f;
        best = fmaxf(best, val);
    }
    out[(long)n * 640 * HWP + (long)c * 4 * HWP + p * 4 + b] = best;
}

// ---------------------------------------------------------------------------
extern "C" void kernel_launch(void* const* d_in, const int* in_sizes, int n_in,
                              void* d_out, int out_size)
{
    const float* feature  = (const float*)d_in[0];
    const float* boxes    = (const float*)d_in[1];
    // d_in[2] = wh (unused)
    const float* w_cur    = (const float*)d_in[3];
    const float* b_cur    = (const float*)d_in[4];
    const float* w_ltrb   = (const float*)d_in[5];
    const float* b_ltrb   = (const float*)d_in[6];
    const float* w_mask   = (const float*)d_in[7];
    const float* b_mask   = (const float*)d_in[8];
    const float* w_border = (const float*)d_in[9];
    const float* b_border = (const float*)d_in[10];
    float* out = (float*)d_out;

    float *feat4, *feat4_t, *align, *maskb, *meanp, *rstdp;
    cudaGetSymbolAddress((void**)&feat4,   g_feat4);
    cudaGetSymbolAddress((void**)&feat4_t, g_feat4_t);
    cudaGetSymbolAddress((void**)&align,   g_align);
    cudaGetSymbolAddress((void**)&maskb,   g_mask);
    cudaGetSymbolAddress((void**)&meanp,   g_mean);
    cudaGetSymbolAddress((void**)&rstdp,   g_rstd);

    const long sFeat  = (long)CIN * HWP;
    const long sF4    = (long)512 * HWP;
    const long sAl    = (long)640 * HWP;
    const long sOut   = (long)256 * HWP;

    // Launch order: conv3x3 implicit GEMM is launch index 5 (ncu -s 5 -c 1).
    // 0) fm_short raw conv -> align channels [512..640)
    gemm_tc<0,0><<<dim3(HWP/BN, 128/BM, NB), 256>>>(
        w_cur, feature, nullptr, b_cur, align + 512L*HWP,
        128, CIN, HWP, sFeat, sAl);

    // 1) feat4 raw conv
    gemm_tc<0,0><<<dim3(HWP/BN, 512/BM, NB), 256>>>(
        w_ltrb, feature, nullptr, b_ltrb, feat4,
        512, CIN, HWP, sFeat, sF4);

    // 2) combined instance-norm stats; 3) combined normalize+relu
    stats_kernel<<<dim3(640, NB), 256>>>(feat4, align, meanp, rstdp);
    inorm_relu_kernel<<<dim3(36, 640, NB), 256>>>(feat4, align, meanp, rstdp);

    // 4) channels-last transpose of feat4 for border-align gathers
    transpose_kernel<<<dim3(HWP/32, 4, NB*4), dim3(32, 8)>>>(feat4, feat4_t);

    // 5) mask = sigmoid(conv3x3(feat4))  [implicit GEMM, K = 512*9] — PROFILED
    gemm_tc<2,2><<<dim3(HWP/BN, 640/BM, NB), 256>>>(
        w_mask, feat4, nullptr, b_mask, maskb,
        640, 512*9, HWP, sF4, sAl);

    // 6) border align -> align channels [0..512)
    border_align_kernel<<<dim3(HWP, 4, NB), 128>>>(feat4_t, boxes, align);

    // 7) out = relu(conv1x1(align .* mask))
    gemm_tc<1,1><<<dim3(HWP/BN, 256/BM, NB), 256>>>(
        w_border, align, maskb, b_border, out,
        256, 640, HWP, sAl, sOut);
}